// round 9
// baseline (speedup 1.0000x reference)
#include <cuda_runtime.h>
#include <cstdint>

#define B_  256
#define T_  1000
#define I_  64
#define H_  128
#define G_  384   // 3*H

typedef unsigned long long u64;

// Scratch for the precomputed input projection x_proj[B][T][3H] (bias folded in).
__device__ float g_xproj[(size_t)B_ * T_ * G_];

// ---- packed fp32x2 helpers (sm_100+) ----------------------------------------
__device__ __forceinline__ u64 fma2(u64 a, u64 b, u64 c) {
    u64 d;
    asm("fma.rn.f32x2 %0, %1, %2, %3;" : "=l"(d) : "l"(a), "l"(b), "l"(c));
    return d;
}
__device__ __forceinline__ float sum2(u64 a) {
    unsigned lo, hi;
    asm("mov.b64 {%0, %1}, %2;" : "=r"(lo), "=r"(hi) : "l"(a));
    return __uint_as_float(lo) + __uint_as_float(hi);
}
__device__ __forceinline__ float tanha(float x) {
    float y;
    asm("tanh.approx.f32 %0, %1;" : "=f"(y) : "f"(x));
    return y;
}
__device__ __forceinline__ void cp_async16(uint32_t s, const void* g) {
    asm volatile("cp.async.ca.shared.global [%0], [%1], 16;" :: "r"(s), "l"(g));
}

// ---------------------------------------------------------------------------
// Kernel A: persistent x_proj GEMM. 148 CTAs x 512 threads.
// W_ih (full 384x64) lives in SMEM for the whole kernel; 32-row input tiles
// are double-buffered via cp.async so compute never stalls on loads.
// Thread (ty = t>>7, tx = t&127): 8 rows x 3 cols, paired-k fma2.
// ---------------------------------------------------------------------------
#define XP_NT   ((B_ * T_) / 32)   // 8000 tiles
#define XP_GRID 148

__global__ __launch_bounds__(512) void xproj_kernel(
    const float* __restrict__ input,
    const float* __restrict__ W_ih,
    const float* __restrict__ b_ih)
{
    extern __shared__ __align__(16) u64 xsm[];
    u64* Ws   = xsm;                  // [384][34] k-pairs (pad 34 -> no conflicts)
    u64* bufA = xsm + 384 * 34;       // 2 x [32][34] k-pairs

    const int t = threadIdx.x;
    const int tx = t & 127;
    const int ty = t >> 7;            // warp-uniform

    // W_ih -> SMEM once (coalesced).
    {
        const u64* wu = (const u64*)W_ih;
        #pragma unroll
        for (int p = 0; p < 24; ++p) {
            int idx = t + p * 512;
            Ws[(idx >> 5) * 34 + (idx & 31)] = wu[idx];
        }
    }
    float bias[3];
    #pragma unroll
    for (int jn = 0; jn < 3; ++jn) bias[jn] = b_ih[tx + jn * 128];

    // Per-thread cp.async source/dest for a 32x64 tile (16B each).
    const int pr  = t >> 4;          // tile row 0..31
    const int pc  = t & 15;          // 16B chunk 0..15
    uint32_t dst0 = (uint32_t)__cvta_generic_to_shared(&bufA[pr * 34 + pc * 2]);
    uint32_t dst1 = (uint32_t)__cvta_generic_to_shared(&bufA[1088 + pr * 34 + pc * 2]);

    // Prefetch first tile.
    int tile = blockIdx.x;
    if (tile < XP_NT) {
        cp_async16(dst0, input + ((size_t)tile * 32 + pr) * I_ + pc * 4);
        asm volatile("cp.async.commit_group;");
    }

    int p = 0;
    for (; tile < XP_NT; tile += XP_GRID) {
        asm volatile("cp.async.wait_group 0;");
        __syncthreads();
        if (tile + XP_GRID < XP_NT) {
            cp_async16(p ? dst0 : dst1,
                       input + ((size_t)(tile + XP_GRID) * 32 + pr) * I_ + pc * 4);
            asm volatile("cp.async.commit_group;");
        }

        const u64* A = bufA + p * 1088;
        u64 acc[8][3];
        #pragma unroll
        for (int i = 0; i < 8; ++i)
            #pragma unroll
            for (int jn = 0; jn < 3; ++jn) acc[i][jn] = 0;

        #pragma unroll
        for (int kk2 = 0; kk2 < 16; ++kk2) {
            ulonglong2 a2[8], b2[3];
            #pragma unroll
            for (int i = 0; i < 8; ++i)
                a2[i] = *(const ulonglong2*)&A[(ty * 8 + i) * 34 + 2 * kk2];
            #pragma unroll
            for (int jn = 0; jn < 3; ++jn)
                b2[jn] = *(const ulonglong2*)&Ws[(tx + jn * 128) * 34 + 2 * kk2];
            #pragma unroll
            for (int i = 0; i < 8; ++i)
                #pragma unroll
                for (int jn = 0; jn < 3; ++jn) {
                    acc[i][jn] = fma2(a2[i].x, b2[jn].x, acc[i][jn]);
                    acc[i][jn] = fma2(a2[i].y, b2[jn].y, acc[i][jn]);
                }
        }

        #pragma unroll
        for (int i = 0; i < 8; ++i) {
            float* orow = g_xproj + ((size_t)tile * 32 + ty * 8 + i) * G_;
            #pragma unroll
            for (int jn = 0; jn < 3; ++jn)
                orow[tx + jn * 128] = sum2(acc[i][jn]) + bias[jn];
        }
        p ^= 1;
    }
}

// ---------------------------------------------------------------------------
// Kernel B: GRU recurrence. 128 CTAs x 512 threads, 2 batches per CTA.
// Thread (j = t>>2, q = t&3): k-quarter q of gate rows {j, j+128, j+256},
// both batches — the 4 quarters of a unit sit in ONE warp, so the k-reduction
// is 2 shfl.bfly (no smem round-trip, ONE barrier/step). Gates r,z in regs
// (32 u64); gate n from SMEM (layout [m][j][q], bank-skewed, LDS.128).
// h double-buffered in SMEM (layout [kk][q][b] -> 1-wf broadcast LDS.128).
// ---------------------------------------------------------------------------
__global__ __launch_bounds__(512, 1) void gru_kernel(
    const float* __restrict__ W_hh,
    const float* __restrict__ b_hh,
    float* __restrict__ out)
{
    extern __shared__ __align__(16) ulonglong2 Wn[];   // [8 m][128 j][4 q] = 65536 B
    __shared__ __align__(16) u64 hbuf[2][128];         // [phase][(kk*4+q)*2+b]

    const int t = threadIdx.x;
    const int j = t >> 2;
    const int q = t & 3;
    const int b0 = blockIdx.x * 2;

    const u64* W2u = (const u64*)W_hh;                 // W_hh[g][k] as k-pairs

    // Gates r,z quarter-slices -> registers (32 u64 = 64 regs).
    u64 wreg[32];
    #pragma unroll
    for (int gi = 0; gi < 2; ++gi)
        #pragma unroll
        for (int kk = 0; kk < 16; ++kk)
            wreg[gi * 16 + kk] = W2u[(size_t)(gi * 128 + j) * 64 + q * 16 + kk];

    // Gate-n -> SMEM: Wn[(m*128 + jj)*4 + qq] = {k2 = qq*16+2m, +2m+1} of row jj.
    for (int idx = t; idx < 4096; idx += 512) {
        int qq = idx & 3;
        int jj = (idx >> 2) & 127;
        int m  = idx >> 9;
        const u64* src = &W2u[(size_t)(2 * 128 + jj) * 64 + qq * 16 + 2 * m];
        ulonglong2 v; v.x = src[0]; v.y = src[1];
        Wn[idx] = v;
    }

    const float bh0 = b_hh[j];
    const float bh1 = b_hh[j + 128];
    const float bh2 = b_hh[j + 256];

    if (t < 128) hbuf[0][t] = 0;
    float hreg = 0.f;

    const int qb = q & 1;          // batch for epilogue lanes (q<2); clamp others
    const float* xp  = g_xproj + (size_t)(b0 + qb) * T_ * G_ + j;
    float*       stp = out     + (size_t)(b0 + qb) * T_ * H_ + j;

    // Per-thread h-store slot: k2 = j>>1 lives at (kk= k2&15, qq = k2>>4).
    const int k2s = j >> 1;
    const int hw  = ((((k2s & 15) * 4 + (k2s >> 4)) * 2 + qb) * 2) + (j & 1);

    const ulonglong2* wnp = Wn + j * 4 + q;            // stride 512 per m
    int p = 0;
    __syncthreads();

    for (int step = 0; step < T_; ++step) {
        float xr = 0.f, xz = 0.f, xn = 0.f;
        if (q < 2) { xr = xp[0]; xz = xp[128]; xn = xp[256]; }

        const ulonglong2* hvec = (const ulonglong2*)hbuf[p];  // [kk*4 + q]
        u64 a00 = 0, a01 = 0, a10 = 0, a11 = 0, a20 = 0, a21 = 0;
        ulonglong2 w2 = wnp[0];
        #pragma unroll
        for (int m = 0; m < 8; ++m) {
            ulonglong2 h2a = hvec[(2 * m) * 4 + q];        // 1-wf broadcast
            ulonglong2 h2b = hvec[(2 * m + 1) * 4 + q];
            ulonglong2 w2c = w2;
            if (m < 7) w2 = wnp[(m + 1) * 512];            // prefetch next
            a00 = fma2(wreg[2 * m],          h2a.x, a00);
            a01 = fma2(wreg[2 * m],          h2a.y, a01);
            a10 = fma2(wreg[16 + 2 * m],     h2a.x, a10);
            a11 = fma2(wreg[16 + 2 * m],     h2a.y, a11);
            a20 = fma2(w2c.x,                h2a.x, a20);
            a21 = fma2(w2c.x,                h2a.y, a21);
            a00 = fma2(wreg[2 * m + 1],      h2b.x, a00);
            a01 = fma2(wreg[2 * m + 1],      h2b.y, a01);
            a10 = fma2(wreg[16 + 2 * m + 1], h2b.x, a10);
            a11 = fma2(wreg[16 + 2 * m + 1], h2b.y, a11);
            a20 = fma2(w2c.y,                h2b.x, a20);
            a21 = fma2(w2c.y,                h2b.y, a21);
        }

        // In-warp reduction over the 4 k-quarters (lanes xor 1, xor 2).
        float r0 = sum2(a00), r1 = sum2(a01);
        float z0 = sum2(a10), z1 = sum2(a11);
        float n0 = sum2(a20), n1 = sum2(a21);
        #define RED_(v) \
            v += __shfl_xor_sync(0xffffffffu, v, 1); \
            v += __shfl_xor_sync(0xffffffffu, v, 2);
        RED_(r0) RED_(r1) RED_(z0) RED_(z1) RED_(n0) RED_(n1)
        #undef RED_

        if (q < 2) {                                   // lane's batch b = q
            const float hr = (q == 0 ? r0 : r1) + bh0;
            const float hz = (q == 0 ? z0 : z1) + bh1;
            const float hn = (q == 0 ? n0 : n1) + bh2;

            const float r = 0.5f + 0.5f * tanha(0.5f * (xr + hr));
            const float z = 0.5f + 0.5f * tanha(0.5f * (xz + hz));
            const float n = tanha(xn + r * hn);
            hreg = n + z * (hreg - n);

            ((float*)hbuf[p ^ 1])[hw] = hreg;          // write NEW phase
            stp[0] = hreg;
        }
        xp  += G_;
        stp += H_;
        p ^= 1;
        __syncthreads();                               // single barrier/step
    }

    if (q < 2)
        out[(size_t)B_ * T_ * H_ + (size_t)(b0 + qb) * H_ + j] = hreg;
}

// ---------------------------------------------------------------------------
// Launcher
// ---------------------------------------------------------------------------
extern "C" void kernel_launch(void* const* d_in, const int* in_sizes, int n_in,
                              void* d_out, int out_size)
{
    const float* input = (const float*)d_in[0];   // [B, T, I]
    const float* W_ih  = (const float*)d_in[1];   // [3H, I]
    const float* W_hh  = (const float*)d_in[2];   // [3H, H]
    const float* b_ih  = (const float*)d_in[3];   // [3H]
    const float* b_hh  = (const float*)d_in[4];   // [3H]
    float* out = (float*)d_out;

    const int xp_smem = (384 * 34 + 2 * 32 * 34) * 8;   // 121856 B
    cudaFuncSetAttribute(xproj_kernel, cudaFuncAttributeMaxDynamicSharedMemorySize,
                         xp_smem);
    const int gru_smem = 65536;                          // Wn (hbuf is static)
    cudaFuncSetAttribute(gru_kernel, cudaFuncAttributeMaxDynamicSharedMemorySize,
                         gru_smem);

    xproj_kernel<<<XP_GRID, 512, xp_smem>>>(input, W_ih, b_ih);
    gru_kernel<<<B_ / 2, 512, gru_smem>>>(W_hh, b_hh, out);
}

// round 10
// speedup vs baseline: 1.1635x; 1.1635x over previous
#include <cuda_runtime.h>
#include <cstdint>

#define B_  256
#define T_  1000
#define I_  64
#define H_  128
#define G_  384   // 3*H

typedef unsigned long long u64;

// Scratch for the precomputed input projection x_proj[B][T][3H] (bias folded in).
__device__ float g_xproj[(size_t)B_ * T_ * G_];

// ---- packed fp32x2 helpers (sm_100+) ----------------------------------------
__device__ __forceinline__ u64 fma2(u64 a, u64 b, u64 c) {
    u64 d;
    asm("fma.rn.f32x2 %0, %1, %2, %3;" : "=l"(d) : "l"(a), "l"(b), "l"(c));
    return d;
}
__device__ __forceinline__ float sum2(u64 a) {
    unsigned lo, hi;
    asm("mov.b64 {%0, %1}, %2;" : "=r"(lo), "=r"(hi) : "l"(a));
    return __uint_as_float(lo) + __uint_as_float(hi);
}
__device__ __forceinline__ float tanha(float x) {
    float y;
    asm("tanh.approx.f32 %0, %1;" : "=f"(y) : "f"(x));
    return y;
}
__device__ __forceinline__ void cp_async16(uint32_t s, const void* g) {
    asm volatile("cp.async.ca.shared.global [%0], [%1], 16;" :: "r"(s), "l"(g));
}

// ---------------------------------------------------------------------------
// Kernel A: persistent x_proj GEMM. 148 CTAs x 512 threads.
// W_ih (full 384x64) lives in SMEM for the whole kernel; 32-row input tiles
// are double-buffered via cp.async so compute never stalls on loads.
// Thread (ty = t>>7, tx = t&127): 8 rows x 3 cols, paired-k fma2.
// ---------------------------------------------------------------------------
#define XP_NT   ((B_ * T_) / 32)   // 8000 tiles
#define XP_GRID 148

__global__ __launch_bounds__(512) void xproj_kernel(
    const float* __restrict__ input,
    const float* __restrict__ W_ih,
    const float* __restrict__ b_ih)
{
    extern __shared__ __align__(16) u64 xsm[];
    u64* Ws   = xsm;                  // [384][34] k-pairs (pad 34)
    u64* bufA = xsm + 384 * 34;       // 2 x [32][34] k-pairs

    const int t = threadIdx.x;
    const int tx = t & 127;
    const int ty = t >> 7;            // warp-uniform

    // W_ih -> SMEM once (coalesced).
    {
        const u64* wu = (const u64*)W_ih;
        #pragma unroll
        for (int p = 0; p < 24; ++p) {
            int idx = t + p * 512;
            Ws[(idx >> 5) * 34 + (idx & 31)] = wu[idx];
        }
    }
    float bias[3];
    #pragma unroll
    for (int jn = 0; jn < 3; ++jn) bias[jn] = b_ih[tx + jn * 128];

    // Per-thread cp.async source/dest for a 32x64 tile (16B each).
    const int pr  = t >> 4;          // tile row 0..31
    const int pc  = t & 15;          // 16B chunk 0..15
    uint32_t dst0 = (uint32_t)__cvta_generic_to_shared(&bufA[pr * 34 + pc * 2]);
    uint32_t dst1 = (uint32_t)__cvta_generic_to_shared(&bufA[1088 + pr * 34 + pc * 2]);

    // Prefetch first tile.
    int tile = blockIdx.x;
    if (tile < XP_NT) {
        cp_async16(dst0, input + ((size_t)tile * 32 + pr) * I_ + pc * 4);
        asm volatile("cp.async.commit_group;");
    }

    int p = 0;
    for (; tile < XP_NT; tile += XP_GRID) {
        asm volatile("cp.async.wait_group 0;");
        __syncthreads();
        if (tile + XP_GRID < XP_NT) {
            cp_async16(p ? dst0 : dst1,
                       input + ((size_t)(tile + XP_GRID) * 32 + pr) * I_ + pc * 4);
            asm volatile("cp.async.commit_group;");
        }

        const u64* A = bufA + p * 1088;
        u64 acc[8][3];
        #pragma unroll
        for (int i = 0; i < 8; ++i)
            #pragma unroll
            for (int jn = 0; jn < 3; ++jn) acc[i][jn] = 0;

        #pragma unroll
        for (int kk2 = 0; kk2 < 16; ++kk2) {
            ulonglong2 a2[8], b2[3];
            #pragma unroll
            for (int i = 0; i < 8; ++i)
                a2[i] = *(const ulonglong2*)&A[(ty * 8 + i) * 34 + 2 * kk2];
            #pragma unroll
            for (int jn = 0; jn < 3; ++jn)
                b2[jn] = *(const ulonglong2*)&Ws[(tx + jn * 128) * 34 + 2 * kk2];
            #pragma unroll
            for (int i = 0; i < 8; ++i)
                #pragma unroll
                for (int jn = 0; jn < 3; ++jn) {
                    acc[i][jn] = fma2(a2[i].x, b2[jn].x, acc[i][jn]);
                    acc[i][jn] = fma2(a2[i].y, b2[jn].y, acc[i][jn]);
                }
        }

        #pragma unroll
        for (int i = 0; i < 8; ++i) {
            float* orow = g_xproj + ((size_t)tile * 32 + ty * 8 + i) * G_;
            #pragma unroll
            for (int jn = 0; jn < 3; ++jn)
                orow[tx + jn * 128] = sum2(acc[i][jn]) + bias[jn];
        }
        p ^= 1;
    }
}

// ---------------------------------------------------------------------------
// Kernel B: GRU recurrence (R8 configuration — best measured: 825us).
// 128 CTAs x 512 threads, 2 batches per CTA. Thread (q = t>>7, j = t&127)
// owns k-quarter q of gate rows {j, j+128, j+256}, both batches. Gates r,z
// in REGISTERS (32 u64); gate n streamed from SMEM as paired ulonglong2 with
// a 1-deep software-pipelined prefetch. h interleaved [k2][b]: one broadcast
// LDS.128 feeds 6 fma2. Partials in part[g][b][q][j] (j contiguous -> 1-wf).
// Warp-specialized epilogue on t<256; nonlinearities via MUFU.TANH.
// ---------------------------------------------------------------------------
__global__ __launch_bounds__(512, 1) void gru_kernel(
    const float* __restrict__ W_hh,
    const float* __restrict__ b_hh,
    float* __restrict__ out)
{
    extern __shared__ __align__(16) char smraw[];
    ulonglong2* Wnp = (ulonglong2*)smraw;            // [32 sid][128 j] = 65536 B
    u64*   hint = (u64*)(smraw + 65536);             // [64 k2][2 b]   = 1024 B
    float* part = (float*)(smraw + 66560);           // [3][2][4][128] = 12288 B

    const int t = threadIdx.x;
    const int j = t & 127;
    const int q = t >> 7;                            // k-quarter; batch for t<256
    const int b0 = blockIdx.x * 2;

    const u64* W2u = (const u64*)W_hh;               // W_hh[g][k] as k-pairs

    // Gates r,z quarter-slices -> registers (32 u64 = 64 regs).
    u64 wreg[32];
    #pragma unroll
    for (int gi = 0; gi < 2; ++gi)
        #pragma unroll
        for (int kk = 0; kk < 16; ++kk)
            wreg[gi * 16 + kk] = W2u[(size_t)(gi * 128 + j) * 64 + q * 16 + kk];

    // Gate-n -> SMEM as paired k2: Wnp[qq*8 + m][g] = {k2=qq*16+2m, +2m+1}.
    for (int idx = t; idx < 32 * 128; idx += 512) {
        int g   = idx & 127;
        int sid = idx >> 7;                          // qq*8 + m
        int qq  = sid >> 3, m = sid & 7;
        const u64* src = &W2u[(size_t)(2 * 128 + g) * 64 + qq * 16 + 2 * m];
        ulonglong2 v; v.x = src[0]; v.y = src[1];
        Wnp[sid * 128 + g] = v;
    }

    const float bh0 = b_hh[j];
    const float bh1 = b_hh[j + 128];
    const float bh2 = b_hh[j + 256];

    if (t < 256) ((float*)hint)[t] = 0.f;
    float hreg = 0.f;

    const int qb = q & 1;   // clamp for safe pointer math on q>=2 threads
    const float* xp  = g_xproj + (size_t)(b0 + qb) * T_ * G_ + j;  // used t<256
    float*       stp = out     + (size_t)(b0 + qb) * T_ * H_ + j;

    const ulonglong2* hvec = (const ulonglong2*)hint;  // [k-pair] -> {b0, b1}
    const ulonglong2* wnp  = Wnp + (q * 8) * 128 + j;  // my gate-n smem slice
    const int hw = (j >> 1) * 4 + q * 2 + (j & 1);     // float slot of h[b=q][j]
    __syncthreads();

    for (int step = 0; step < T_; ++step) {
        // Prefetch this step's input projections (consumed after the barrier).
        float xr = 0.f, xz = 0.f, xn = 0.f;
        if (t < 256) { xr = xp[0]; xz = xp[128]; xn = xp[256]; }

        u64 a00 = 0, a01 = 0, a10 = 0, a11 = 0, a20 = 0, a21 = 0;
        ulonglong2 w2 = wnp[0];                      // software-pipelined W_n
        #pragma unroll
        for (int m = 0; m < 8; ++m) {
            ulonglong2 h2a = hvec[q * 16 + 2 * m];       // broadcast
            ulonglong2 h2b = hvec[q * 16 + 2 * m + 1];   // broadcast
            ulonglong2 w2c = w2;
            if (m < 7) w2 = wnp[(m + 1) * 128];          // prefetch next
            a00 = fma2(wreg[2 * m],          h2a.x, a00);
            a01 = fma2(wreg[2 * m],          h2a.y, a01);
            a10 = fma2(wreg[16 + 2 * m],     h2a.x, a10);
            a11 = fma2(wreg[16 + 2 * m],     h2a.y, a11);
            a20 = fma2(w2c.x,                h2a.x, a20);
            a21 = fma2(w2c.x,                h2a.y, a21);
            a00 = fma2(wreg[2 * m + 1],      h2b.x, a00);
            a01 = fma2(wreg[2 * m + 1],      h2b.y, a01);
            a10 = fma2(wreg[16 + 2 * m + 1], h2b.x, a10);
            a11 = fma2(wreg[16 + 2 * m + 1], h2b.y, a11);
            a20 = fma2(w2c.y,                h2b.x, a20);
            a21 = fma2(w2c.y,                h2b.y, a21);
        }

        // Quarter partials -> SMEM, j contiguous (1 wavefront per store).
        part[((0 * 2 + 0) * 4 + q) * 128 + j] = sum2(a00);
        part[((0 * 2 + 1) * 4 + q) * 128 + j] = sum2(a01);
        part[((1 * 2 + 0) * 4 + q) * 128 + j] = sum2(a10);
        part[((1 * 2 + 1) * 4 + q) * 128 + j] = sum2(a11);
        part[((2 * 2 + 0) * 4 + q) * 128 + j] = sum2(a20);
        part[((2 * 2 + 1) * 4 + q) * 128 + j] = sum2(a21);
        __syncthreads();

        if (t < 256) {                           // b = q
            const float* pr = &part[(0 * 2 + q) * 4 * 128 + j];
            const float* pz = &part[(1 * 2 + q) * 4 * 128 + j];
            const float* pn = &part[(2 * 2 + q) * 4 * 128 + j];
            const float hr = (pr[0] + pr[128]) + (pr[256] + pr[384]) + bh0;
            const float hz = (pz[0] + pz[128]) + (pz[256] + pz[384]) + bh1;
            const float hn = (pn[0] + pn[128]) + (pn[256] + pn[384]) + bh2;

            // sigmoid(x) = 0.5 + 0.5*tanh(0.5x); all via MUFU.TANH.
            const float r = 0.5f + 0.5f * tanha(0.5f * (xr + hr));
            const float z = 0.5f + 0.5f * tanha(0.5f * (xz + hz));
            const float n = tanha(xn + r * hn);
            hreg = n + z * (hreg - n);           // (1-z)n + z*h

            ((float*)hint)[hw] = hreg;
            stp[0] = hreg;
        }
        xp  += G_;
        stp += H_;
        __syncthreads();                         // h visible for next step
    }

    if (t < 256)
        out[(size_t)B_ * T_ * H_ + (size_t)(b0 + q) * H_ + j] = hreg;
}

// ---------------------------------------------------------------------------
// Launcher
// ---------------------------------------------------------------------------
extern "C" void kernel_launch(void* const* d_in, const int* in_sizes, int n_in,
                              void* d_out, int out_size)
{
    const float* input = (const float*)d_in[0];   // [B, T, I]
    const float* W_ih  = (const float*)d_in[1];   // [3H, I]
    const float* W_hh  = (const float*)d_in[2];   // [3H, H]
    const float* b_ih  = (const float*)d_in[3];   // [3H]
    const float* b_hh  = (const float*)d_in[4];   // [3H]
    float* out = (float*)d_out;

    const int xp_smem = (384 * 34 + 2 * 32 * 34) * 8;   // 121856 B
    cudaFuncSetAttribute(xproj_kernel, cudaFuncAttributeMaxDynamicSharedMemorySize,
                         xp_smem);
    const int gru_smem = 65536 + 1024 + 12288;          // 78848 B
    cudaFuncSetAttribute(gru_kernel, cudaFuncAttributeMaxDynamicSharedMemorySize,
                         gru_smem);

    xproj_kernel<<<XP_GRID, 512, xp_smem>>>(input, W_ih, b_ih);
    gru_kernel<<<B_ / 2, 512, gru_smem>>>(W_hh, b_hh, out);
}

// round 11
// speedup vs baseline: 1.1941x; 1.0263x over previous
#include <cuda_runtime.h>
#include <cstdint>

#define B_  256
#define T_  1000
#define I_  64
#define H_  128
#define G_  384   // 3*H

typedef unsigned long long u64;

// Scratch for the precomputed input projection x_proj[B][T][3H] (bias folded in).
__device__ float g_xproj[(size_t)B_ * T_ * G_];

// ---- packed fp32x2 helpers (sm_100+) ----------------------------------------
__device__ __forceinline__ u64 fma2(u64 a, u64 b, u64 c) {
    u64 d;
    asm("fma.rn.f32x2 %0, %1, %2, %3;" : "=l"(d) : "l"(a), "l"(b), "l"(c));
    return d;
}
__device__ __forceinline__ float sum2(u64 a) {
    unsigned lo, hi;
    asm("mov.b64 {%0, %1}, %2;" : "=r"(lo), "=r"(hi) : "l"(a));
    return __uint_as_float(lo) + __uint_as_float(hi);
}
__device__ __forceinline__ float tanha(float x) {
    float y;
    asm("tanh.approx.f32 %0, %1;" : "=f"(y) : "f"(x));
    return y;
}
__device__ __forceinline__ void cp_async16(uint32_t s, const void* g) {
    asm volatile("cp.async.ca.shared.global [%0], [%1], 16;" :: "r"(s), "l"(g));
}

// ---------------------------------------------------------------------------
// Kernel A: persistent x_proj GEMM. 148 CTAs x 512 threads.
// W_ih (full 384x64) lives in SMEM for the whole kernel; 32-row input tiles
// are double-buffered via cp.async so compute never stalls on loads.
// ---------------------------------------------------------------------------
#define XP_NT   ((B_ * T_) / 32)   // 8000 tiles
#define XP_GRID 148

__global__ __launch_bounds__(512) void xproj_kernel(
    const float* __restrict__ input,
    const float* __restrict__ W_ih,
    const float* __restrict__ b_ih)
{
    extern __shared__ __align__(16) u64 xsm[];
    u64* Ws   = xsm;                  // [384][34] k-pairs (pad 34)
    u64* bufA = xsm + 384 * 34;       // 2 x [32][34] k-pairs

    const int t = threadIdx.x;
    const int tx = t & 127;
    const int ty = t >> 7;            // warp-uniform

    {
        const u64* wu = (const u64*)W_ih;
        #pragma unroll
        for (int p = 0; p < 24; ++p) {
            int idx = t + p * 512;
            Ws[(idx >> 5) * 34 + (idx & 31)] = wu[idx];
        }
    }
    float bias[3];
    #pragma unroll
    for (int jn = 0; jn < 3; ++jn) bias[jn] = b_ih[tx + jn * 128];

    const int pr  = t >> 4;
    const int pc  = t & 15;
    uint32_t dst0 = (uint32_t)__cvta_generic_to_shared(&bufA[pr * 34 + pc * 2]);
    uint32_t dst1 = (uint32_t)__cvta_generic_to_shared(&bufA[1088 + pr * 34 + pc * 2]);

    int tile = blockIdx.x;
    if (tile < XP_NT) {
        cp_async16(dst0, input + ((size_t)tile * 32 + pr) * I_ + pc * 4);
        asm volatile("cp.async.commit_group;");
    }

    int p = 0;
    for (; tile < XP_NT; tile += XP_GRID) {
        asm volatile("cp.async.wait_group 0;");
        __syncthreads();
        if (tile + XP_GRID < XP_NT) {
            cp_async16(p ? dst0 : dst1,
                       input + ((size_t)(tile + XP_GRID) * 32 + pr) * I_ + pc * 4);
            asm volatile("cp.async.commit_group;");
        }

        const u64* A = bufA + p * 1088;
        u64 acc[8][3];
        #pragma unroll
        for (int i = 0; i < 8; ++i)
            #pragma unroll
            for (int jn = 0; jn < 3; ++jn) acc[i][jn] = 0;

        #pragma unroll
        for (int kk2 = 0; kk2 < 16; ++kk2) {
            ulonglong2 a2[8], b2[3];
            #pragma unroll
            for (int i = 0; i < 8; ++i)
                a2[i] = *(const ulonglong2*)&A[(ty * 8 + i) * 34 + 2 * kk2];
            #pragma unroll
            for (int jn = 0; jn < 3; ++jn)
                b2[jn] = *(const ulonglong2*)&Ws[(tx + jn * 128) * 34 + 2 * kk2];
            #pragma unroll
            for (int i = 0; i < 8; ++i)
                #pragma unroll
                for (int jn = 0; jn < 3; ++jn) {
                    acc[i][jn] = fma2(a2[i].x, b2[jn].x, acc[i][jn]);
                    acc[i][jn] = fma2(a2[i].y, b2[jn].y, acc[i][jn]);
                }
        }

        #pragma unroll
        for (int i = 0; i < 8; ++i) {
            float* orow = g_xproj + ((size_t)tile * 32 + ty * 8 + i) * G_;
            #pragma unroll
            for (int jn = 0; jn < 3; ++jn)
                orow[tx + jn * 128] = sum2(acc[i][jn]) + bias[jn];
        }
        p ^= 1;
    }
}

// ---------------------------------------------------------------------------
// Kernel B: GRU recurrence. R10 config + 2-deep Wn prefetch that launches in
// the epilogue window (Wn is step-invariant, so the loads for the NEXT step's
// first two m-groups issue right after the part-store barrier, filling the
// otherwise-idle latency of the epilogue on the other warps).
// ---------------------------------------------------------------------------
__global__ __launch_bounds__(512, 1) void gru_kernel(
    const float* __restrict__ W_hh,
    const float* __restrict__ b_hh,
    float* __restrict__ out)
{
    extern __shared__ __align__(16) char smraw[];
    ulonglong2* Wnp = (ulonglong2*)smraw;            // [32 sid][128 j] = 65536 B
    u64*   hint = (u64*)(smraw + 65536);             // [64 k2][2 b]   = 1024 B
    float* part = (float*)(smraw + 66560);           // [3][2][4][128] = 12288 B

    const int t = threadIdx.x;
    const int j = t & 127;
    const int q = t >> 7;                            // k-quarter; batch for t<256
    const int b0 = blockIdx.x * 2;

    const u64* W2u = (const u64*)W_hh;               // W_hh[g][k] as k-pairs

    // Gates r,z quarter-slices -> registers (32 u64 = 64 regs).
    u64 wreg[32];
    #pragma unroll
    for (int gi = 0; gi < 2; ++gi)
        #pragma unroll
        for (int kk = 0; kk < 16; ++kk)
            wreg[gi * 16 + kk] = W2u[(size_t)(gi * 128 + j) * 64 + q * 16 + kk];

    // Gate-n -> SMEM as paired k2: Wnp[qq*8 + m][g] = {k2=qq*16+2m, +2m+1}.
    for (int idx = t; idx < 32 * 128; idx += 512) {
        int g   = idx & 127;
        int sid = idx >> 7;                          // qq*8 + m
        int qq  = sid >> 3, m = sid & 7;
        const u64* src = &W2u[(size_t)(2 * 128 + g) * 64 + qq * 16 + 2 * m];
        ulonglong2 v; v.x = src[0]; v.y = src[1];
        Wnp[sid * 128 + g] = v;
    }

    const float bh0 = b_hh[j];
    const float bh1 = b_hh[j + 128];
    const float bh2 = b_hh[j + 256];

    if (t < 256) ((float*)hint)[t] = 0.f;
    float hreg = 0.f;

    const int qb = q & 1;   // clamp for safe pointer math on q>=2 threads
    const float* xp  = g_xproj + (size_t)(b0 + qb) * T_ * G_ + j;  // used t<256
    float*       stp = out     + (size_t)(b0 + qb) * T_ * H_ + j;

    const ulonglong2* hvec = (const ulonglong2*)hint;  // [k-pair] -> {b0, b1}
    const ulonglong2* wnp  = Wnp + (q * 8) * 128 + j;  // my gate-n smem slice
    const int hw = (j >> 1) * 4 + q * 2 + (j & 1);     // float slot of h[b=q][j]
    __syncthreads();

    // Prime the 2-deep W_n pipeline (step-invariant data).
    ulonglong2 w2a = wnp[0];
    ulonglong2 w2b = wnp[128];

    for (int step = 0; step < T_; ++step) {
        // Prefetch this step's input projections (consumed after the barrier).
        float xr = 0.f, xz = 0.f, xn = 0.f;
        if (t < 256) { xr = xp[0]; xz = xp[128]; xn = xp[256]; }

        u64 a00 = 0, a01 = 0, a10 = 0, a11 = 0, a20 = 0, a21 = 0;
        #pragma unroll
        for (int m = 0; m < 8; ++m) {
            ulonglong2 h2a = hvec[q * 16 + 2 * m];       // broadcast
            ulonglong2 h2b = hvec[q * 16 + 2 * m + 1];   // broadcast
            ulonglong2 w2c = w2a;
            w2a = w2b;
            if (m < 6) w2b = wnp[(m + 2) * 128];         // distance-2 prefetch
            a00 = fma2(wreg[2 * m],          h2a.x, a00);
            a01 = fma2(wreg[2 * m],          h2a.y, a01);
            a10 = fma2(wreg[16 + 2 * m],     h2a.x, a10);
            a11 = fma2(wreg[16 + 2 * m],     h2a.y, a11);
            a20 = fma2(w2c.x,                h2a.x, a20);
            a21 = fma2(w2c.x,                h2a.y, a21);
            a00 = fma2(wreg[2 * m + 1],      h2b.x, a00);
            a01 = fma2(wreg[2 * m + 1],      h2b.y, a01);
            a10 = fma2(wreg[16 + 2 * m + 1], h2b.x, a10);
            a11 = fma2(wreg[16 + 2 * m + 1], h2b.y, a11);
            a20 = fma2(w2c.y,                h2b.x, a20);
            a21 = fma2(w2c.y,                h2b.y, a21);
        }

        // Quarter partials -> SMEM, j contiguous (1 wavefront per store).
        part[((0 * 2 + 0) * 4 + q) * 128 + j] = sum2(a00);
        part[((0 * 2 + 1) * 4 + q) * 128 + j] = sum2(a01);
        part[((1 * 2 + 0) * 4 + q) * 128 + j] = sum2(a10);
        part[((1 * 2 + 1) * 4 + q) * 128 + j] = sum2(a11);
        part[((2 * 2 + 0) * 4 + q) * 128 + j] = sum2(a20);
        part[((2 * 2 + 1) * 4 + q) * 128 + j] = sum2(a21);
        __syncthreads();

        // Re-prime W_n pipeline for the NEXT step NOW — these loads have no
        // dependency on h or part, so they overlap the epilogue below.
        w2a = wnp[0];
        w2b = wnp[128];

        if (t < 256) {                           // b = q
            const float* pr = &part[(0 * 2 + q) * 4 * 128 + j];
            const float* pz = &part[(1 * 2 + q) * 4 * 128 + j];
            const float* pn = &part[(2 * 2 + q) * 4 * 128 + j];
            // Issue all 12 reduction loads before combining (ILP over LDS).
            float r0 = pr[0], r1 = pr[128], r2 = pr[256], r3 = pr[384];
            float z0 = pz[0], z1 = pz[128], z2 = pz[256], z3 = pz[384];
            float n0 = pn[0], n1 = pn[128], n2 = pn[256], n3 = pn[384];
            const float hr = (r0 + r1) + (r2 + r3) + bh0;
            const float hz = (z0 + z1) + (z2 + z3) + bh1;
            const float hn = (n0 + n1) + (n2 + n3) + bh2;

            // sigmoid(x) = 0.5 + 0.5*tanh(0.5x); all via MUFU.TANH.
            const float r = 0.5f + 0.5f * tanha(0.5f * (xr + hr));
            const float z = 0.5f + 0.5f * tanha(0.5f * (xz + hz));
            const float n = tanha(xn + r * hn);
            hreg = n + z * (hreg - n);           // (1-z)n + z*h

            ((float*)hint)[hw] = hreg;
            stp[0] = hreg;
        }
        xp  += G_;
        stp += H_;
        __syncthreads();                         // h visible for next step
    }

    if (t < 256)
        out[(size_t)B_ * T_ * H_ + (size_t)(b0 + q) * H_ + j] = hreg;
}

// ---------------------------------------------------------------------------
// Launcher
// ---------------------------------------------------------------------------
extern "C" void kernel_launch(void* const* d_in, const int* in_sizes, int n_in,
                              void* d_out, int out_size)
{
    const float* input = (const float*)d_in[0];   // [B, T, I]
    const float* W_ih  = (const float*)d_in[1];   // [3H, I]
    const float* W_hh  = (const float*)d_in[2];   // [3H, H]
    const float* b_ih  = (const float*)d_in[3];   // [3H]
    const float* b_hh  = (const float*)d_in[4];   // [3H]
    float* out = (float*)d_out;

    const int xp_smem = (384 * 34 + 2 * 32 * 34) * 8;   // 121856 B
    cudaFuncSetAttribute(xproj_kernel, cudaFuncAttributeMaxDynamicSharedMemorySize,
                         xp_smem);
    const int gru_smem = 65536 + 1024 + 12288;          // 78848 B
    cudaFuncSetAttribute(gru_kernel, cudaFuncAttributeMaxDynamicSharedMemorySize,
                         gru_smem);

    xproj_kernel<<<XP_GRID, 512, xp_smem>>>(input, W_ih, b_ih);
    gru_kernel<<<B_ / 2, 512, gru_smem>>>(W_hh, b_hh, out);
}